// round 2
// baseline (speedup 1.0000x reference)
#include <cuda_runtime.h>

// stepSSM fused kernel: fc1 -> 4x (complex SSM step -> leaky_relu(0.125) -> fc 2x2) -> fc10
// One thread per row. Pure HBM-streaming problem (~536 MB traffic, ~0.2 GFLOP).
//
// Input order (metadata):
//   0: x       [B,4]        f32
//   1: states  [4,B,2,4,2]  f32
//   2: fc1_w   [2,4]
//   3: fc1_b   [2]
//   4: fc_w    [5,2,2]
//   5: fc_b    [5,2]
//   6: A       [4,2,4,2]
//   7: Bm      [4,2,4,2]
//   8: C       [4,1,2,4,2]
//   9: D       [4,1,2]
// Output: h [B,2] followed by new_states [4,B,2,4,2] (both f32, concatenated).

#define THREADS 256

// shared-constant packing offsets
#define OFF_FC1W 0    // 8
#define OFF_FC1B 8    // 2
#define OFF_FCW  10   // 20
#define OFF_FCB  30   // 10
#define OFF_A    40   // 64
#define OFF_BM   104  // 64
#define OFF_C    168  // 64
#define OFF_D    232  // 8
#define N_CONST  240

__global__ __launch_bounds__(THREADS) void step_ssm_kernel(
    const float4* __restrict__ x,        // [B] of float4
    const float*  __restrict__ states,   // [4,B,16]
    const float*  __restrict__ fc1_w,
    const float*  __restrict__ fc1_b,
    const float*  __restrict__ fc_w,
    const float*  __restrict__ fc_b,
    const float*  __restrict__ A,
    const float*  __restrict__ Bm,
    const float*  __restrict__ C,
    const float*  __restrict__ D,
    float2*       __restrict__ out_h,      // [B]
    float*        __restrict__ out_states, // [4,B,16]
    int B)
{
    __shared__ float sc[N_CONST];
    {
        int t = threadIdx.x;
        if (t < N_CONST) {
            float v;
            if      (t < OFF_FC1B) v = fc1_w[t - OFF_FC1W];
            else if (t < OFF_FCW)  v = fc1_b[t - OFF_FC1B];
            else if (t < OFF_FCB)  v = fc_w [t - OFF_FCW];
            else if (t < OFF_A)    v = fc_b [t - OFF_FCB];
            else if (t < OFF_BM)   v = A    [t - OFF_A];
            else if (t < OFF_C)    v = Bm   [t - OFF_BM];
            else if (t < OFF_D)    v = C    [t - OFF_C];
            else                   v = D    [t - OFF_D];
            sc[t] = v;
        }
    }
    __syncthreads();

    int n = blockIdx.x * blockDim.x + threadIdx.x;
    if (n >= B) return;

    // fc1: [N,4] @ [2,4]^T + b
    float4 xv = x[n];
    float h0 = fmaf(xv.x, sc[OFF_FC1W + 0], fmaf(xv.y, sc[OFF_FC1W + 1],
               fmaf(xv.z, sc[OFF_FC1W + 2], fmaf(xv.w, sc[OFF_FC1W + 3], sc[OFF_FC1B + 0]))));
    float h1 = fmaf(xv.x, sc[OFF_FC1W + 4], fmaf(xv.y, sc[OFF_FC1W + 5],
               fmaf(xv.z, sc[OFF_FC1W + 6], fmaf(xv.w, sc[OFF_FC1W + 7], sc[OFF_FC1B + 1]))));

    const size_t row_off   = (size_t)n * 16;
    const size_t layer_str = (size_t)B * 16;

#pragma unroll
    for (int i = 0; i < 4; i++) {
        const float4* sp = reinterpret_cast<const float4*>(states + (size_t)i * layer_str + row_off);
        float4 v0 = sp[0], v1 = sp[1], v2 = sp[2], v3 = sp[3];
        float st[16] = { v0.x, v0.y, v0.z, v0.w,
                         v1.x, v1.y, v1.z, v1.w,
                         v2.x, v2.y, v2.z, v2.w,
                         v3.x, v3.y, v3.z, v3.w };
        float ns[16];
        float acc0 = 0.0f, acc1 = 0.0f;
        const int lb = i * 16;

#pragma unroll
        for (int hd = 0; hd < 2; hd++) {
            float u   = (hd == 0) ? h0 : h1;
            float acc = 0.0f;
#pragma unroll
            for (int f = 0; f < 4; f++) {
                int k  = hd * 8 + f * 2;
                float sr = st[k], si = st[k + 1];
                float Ar = sc[OFF_A  + lb + k], Ai = sc[OFF_A  + lb + k + 1];
                float Br = sc[OFF_BM + lb + k], Bi = sc[OFF_BM + lb + k + 1];
                float nr = fmaf(Ar, sr, fmaf(-Ai, si, Br * u));
                float ni = fmaf(Ar, si, fmaf( Ai, sr, Bi * u));
                ns[k]     = nr;
                ns[k + 1] = ni;
                float Cr = sc[OFF_C + lb + k], Ci = sc[OFF_C + lb + k + 1];
                acc = fmaf(Cr, nr, fmaf(-Ci, ni, acc));
            }
            if (hd == 0) acc0 = acc; else acc1 = acc;
        }

        // write new state (coalesced float4)
        float4* op = reinterpret_cast<float4*>(out_states + (size_t)i * layer_str + row_off);
        op[0] = make_float4(ns[0],  ns[1],  ns[2],  ns[3]);
        op[1] = make_float4(ns[4],  ns[5],  ns[6],  ns[7]);
        op[2] = make_float4(ns[8],  ns[9],  ns[10], ns[11]);
        op[3] = make_float4(ns[12], ns[13], ns[14], ns[15]);

        // y = 2*Re(...) + u*D ; leaky_relu(0.125) ; fc_i (2x2)
        float y0 = fmaf(2.0f, acc0, h0 * sc[OFF_D + i * 2 + 0]);
        float y1 = fmaf(2.0f, acc1, h1 * sc[OFF_D + i * 2 + 1]);
        y0 = (y0 >= 0.0f) ? y0 : 0.125f * y0;
        y1 = (y1 >= 0.0f) ? y1 : 0.125f * y1;

        const int wb = OFF_FCW + i * 4;
        float nh0 = fmaf(y0, sc[wb + 0], fmaf(y1, sc[wb + 1], sc[OFF_FCB + i * 2 + 0]));
        float nh1 = fmaf(y0, sc[wb + 2], fmaf(y1, sc[wb + 3], sc[OFF_FCB + i * 2 + 1]));
        h0 = nh0;
        h1 = nh1;
    }

    // fc10
    const int wb = OFF_FCW + 16;
    float o0 = fmaf(h0, sc[wb + 0], fmaf(h1, sc[wb + 1], sc[OFF_FCB + 8]));
    float o1 = fmaf(h0, sc[wb + 2], fmaf(h1, sc[wb + 3], sc[OFF_FCB + 9]));
    out_h[n] = make_float2(o0, o1);
}

extern "C" void kernel_launch(void* const* d_in, const int* in_sizes, int n_in,
                              void* d_out, int out_size)
{
    const float* x     = (const float*)d_in[0];
    const float* states= (const float*)d_in[1];
    const float* fc1_w = (const float*)d_in[2];
    const float* fc1_b = (const float*)d_in[3];
    const float* fc_w  = (const float*)d_in[4];
    const float* fc_b  = (const float*)d_in[5];
    const float* A     = (const float*)d_in[6];
    const float* Bm    = (const float*)d_in[7];
    const float* C     = (const float*)d_in[8];
    const float* D     = (const float*)d_in[9];

    int B = in_sizes[0] / 4;  // x is [B,4]

    float* out   = (float*)d_out;
    float2* oh   = (float2*)out;          // h: [B,2]
    float* ost   = out + (size_t)2 * B;   // new_states: [4,B,2,4,2]

    int grid = (B + THREADS - 1) / THREADS;
    step_ssm_kernel<<<grid, THREADS>>>(
        (const float4*)x, states, fc1_w, fc1_b, fc_w, fc_b, A, Bm, C, D,
        oh, ost, B);
}

// round 3
// speedup vs baseline: 1.2142x; 1.2142x over previous
#include <cuda_runtime.h>

// stepSSM fused kernel, R3: 4 threads per row for fully-coalesced state I/O.
//
// Row state = 16 floats = 4x float4. Thread quad (q = tid&3) each owns one
// float4 => lane-consecutive addresses => 4 L1 wavefronts per LDG.128 instead
// of 16 (R2's 64B-stride pattern). Cross-thread coupling handled with two
// shfl_xor per layer (C-reduction over f, y exchange across heads).
//
// Mapping: q=0 -> head0 f0,f1 ; q=1 -> head0 f2,f3 ; q=2 -> head1 f0,f1 ;
//          q=3 -> head1 f2,f3.  (k = q*4 .. q*4+3 in the [2,4,2] re/im layout)
//
// Inputs (metadata order):
//   0: x[B,4]  1: states[4,B,2,4,2]  2: fc1_w[2,4]  3: fc1_b[2]
//   4: fc_w[5,2,2]  5: fc_b[5,2]  6: A[4,2,4,2]  7: Bm[4,2,4,2]
//   8: C[4,1,2,4,2]  9: D[4,1,2]
// Output: h[B,2] ++ new_states[4,B,2,4,2]  (f32)

#define THREADS 256

#define OFF_FC1W 0    // 8
#define OFF_FC1B 8    // 2
#define OFF_FCW  10   // 20
#define OFF_FCB  30   // 10
#define OFF_A    40   // 64
#define OFF_BM   104  // 64
#define OFF_C    168  // 64
#define OFF_D    232  // 8
#define N_CONST  240

__global__ __launch_bounds__(THREADS) void step_ssm_kernel(
    const float4* __restrict__ x,        // [B]
    const float4* __restrict__ states,   // [4*B*4] float4
    const float*  __restrict__ fc1_w,
    const float*  __restrict__ fc1_b,
    const float*  __restrict__ fc_w,
    const float*  __restrict__ fc_b,
    const float*  __restrict__ A,
    const float*  __restrict__ Bm,
    const float*  __restrict__ C,
    const float*  __restrict__ D,
    float2*       __restrict__ out_h,      // [B]
    float4*       __restrict__ out_states, // [4*B*4] float4
    int B)
{
    __shared__ float sc[N_CONST];
    {
        int t = threadIdx.x;
        if (t < N_CONST) {
            float v;
            if      (t < OFF_FC1B) v = fc1_w[t - OFF_FC1W];
            else if (t < OFF_FCW)  v = fc1_b[t - OFF_FC1B];
            else if (t < OFF_FCB)  v = fc_w [t - OFF_FCW];
            else if (t < OFF_A)    v = fc_b [t - OFF_FCB];
            else if (t < OFF_BM)   v = A    [t - OFF_A];
            else if (t < OFF_C)    v = Bm   [t - OFF_BM];
            else if (t < OFF_D)    v = C    [t - OFF_C];
            else                   v = D    [t - OFF_D];
            sc[t] = v;
        }
    }
    __syncthreads();

    const int t   = blockIdx.x * blockDim.x + threadIdx.x;
    const int row = t >> 2;
    const int q   = t & 3;
    if (row >= B) return;

    // Front-load all global reads for MLP: x (broadcast within quad) + 4 state tiles.
    const size_t layer_str = (size_t)B * 4;           // float4 units
    const size_t my_off    = (size_t)row * 4 + q;

    float4 st[4];
#pragma unroll
    for (int i = 0; i < 4; i++)
        st[i] = __ldcs(states + (size_t)i * layer_str + my_off);

    float4 xv = __ldg(reinterpret_cast<const float4*>(x) + row);

    // fc1 (replicated across the quad)
    float h0 = fmaf(xv.x, sc[OFF_FC1W + 0], fmaf(xv.y, sc[OFF_FC1W + 1],
               fmaf(xv.z, sc[OFF_FC1W + 2], fmaf(xv.w, sc[OFF_FC1W + 3], sc[OFF_FC1B + 0]))));
    float h1 = fmaf(xv.x, sc[OFF_FC1W + 4], fmaf(xv.y, sc[OFF_FC1W + 5],
               fmaf(xv.z, sc[OFF_FC1W + 6], fmaf(xv.w, sc[OFF_FC1W + 7], sc[OFF_FC1B + 1]))));

    const int hd = q >> 1;              // this thread's head
    const int kq = q * 4;               // base k within the 16-float row

#pragma unroll
    for (int i = 0; i < 4; i++) {
        const int lb = i * 16 + kq;
        const float u = (hd == 0) ? h0 : h1;

        // two complex (f) pairs: (st.x,st.y) and (st.z,st.w)
        float Ar0 = sc[OFF_A  + lb + 0], Ai0 = sc[OFF_A  + lb + 1];
        float Ar1 = sc[OFF_A  + lb + 2], Ai1 = sc[OFF_A  + lb + 3];
        float Br0 = sc[OFF_BM + lb + 0], Bi0 = sc[OFF_BM + lb + 1];
        float Br1 = sc[OFF_BM + lb + 2], Bi1 = sc[OFF_BM + lb + 3];
        float Cr0 = sc[OFF_C  + lb + 0], Ci0 = sc[OFF_C  + lb + 1];
        float Cr1 = sc[OFF_C  + lb + 2], Ci1 = sc[OFF_C  + lb + 3];

        float nr0 = fmaf(Ar0, st[i].x, fmaf(-Ai0, st[i].y, Br0 * u));
        float ni0 = fmaf(Ar0, st[i].y, fmaf( Ai0, st[i].x, Bi0 * u));
        float nr1 = fmaf(Ar1, st[i].z, fmaf(-Ai1, st[i].w, Br1 * u));
        float ni1 = fmaf(Ar1, st[i].w, fmaf( Ai1, st[i].z, Bi1 * u));

        // coalesced streaming store of this thread's quarter of the new state
        __stcs(out_states + (size_t)i * layer_str + my_off,
               make_float4(nr0, ni0, nr1, ni1));

        // partial C-projection for this thread's 2 f's, then reduce over the
        // 2 threads sharing a head (xor 1)
        float acc = fmaf(Cr0, nr0, fmaf(-Ci0, ni0,
                    fmaf(Cr1, nr1, -Ci1 * ni1)));
        acc += __shfl_xor_sync(0xFFFFFFFFu, acc, 1);

        // y for own head, activation, then swap heads (xor 2)
        float y = fmaf(2.0f, acc, u * sc[OFF_D + i * 2 + hd]);
        y = (y >= 0.0f) ? y : 0.125f * y;
        float yo = __shfl_xor_sync(0xFFFFFFFFu, y, 2);
        float y0 = (hd == 0) ? y  : yo;
        float y1 = (hd == 0) ? yo : y;

        const int wb = OFF_FCW + i * 4;
        h0 = fmaf(y0, sc[wb + 0], fmaf(y1, sc[wb + 1], sc[OFF_FCB + i * 2 + 0]));
        h1 = fmaf(y0, sc[wb + 2], fmaf(y1, sc[wb + 3], sc[OFF_FCB + i * 2 + 1]));
    }

    // fc10 — one lane per row writes the contiguous float2
    if (q == 0) {
        const int wb = OFF_FCW + 16;
        float o0 = fmaf(h0, sc[wb + 0], fmaf(h1, sc[wb + 1], sc[OFF_FCB + 8]));
        float o1 = fmaf(h0, sc[wb + 2], fmaf(h1, sc[wb + 3], sc[OFF_FCB + 9]));
        out_h[row] = make_float2(o0, o1);
    }
}

extern "C" void kernel_launch(void* const* d_in, const int* in_sizes, int n_in,
                              void* d_out, int out_size)
{
    const float* x     = (const float*)d_in[0];
    const float* states= (const float*)d_in[1];
    const float* fc1_w = (const float*)d_in[2];
    const float* fc1_b = (const float*)d_in[3];
    const float* fc_w  = (const float*)d_in[4];
    const float* fc_b  = (const float*)d_in[5];
    const float* A     = (const float*)d_in[6];
    const float* Bm    = (const float*)d_in[7];
    const float* C     = (const float*)d_in[8];
    const float* D     = (const float*)d_in[9];

    int B = in_sizes[0] / 4;  // x is [B,4]

    float*  out = (float*)d_out;
    float2* oh  = (float2*)out;                  // h: [B,2]
    float4* ost = (float4*)(out + (size_t)2 * B); // new_states: [4,B,2,4,2]

    long long total = (long long)B * 4;          // 4 threads per row
    int grid = (int)((total + THREADS - 1) / THREADS);
    step_ssm_kernel<<<grid, THREADS>>>(
        (const float4*)x, (const float4*)states,
        fc1_w, fc1_b, fc_w, fc_b, A, Bm, C, D,
        oh, ost, B);
}